// round 3
// baseline (speedup 1.0000x reference)
#include <cuda_runtime.h>
#include <cuda_bf16.h>
#include <math.h>

#define R 512
#define K 81
#define NMS_THRESH 0.5f
#define SCORE_THRESH 0.001f
#define MAX_PER_IMG 100
#define POST_NMS_TOPN 300
#define XFORM_CLIP 4.135166556742356f  /* log(1000/16) */
#define IM_W_M1 1332.0f
#define IM_H_M1 799.0f

// Scratch (no allocation allowed in kernel_launch)
__device__ float g_boxes[R * K * 4];   // [r][k][4]
__device__ float g_dist[R * K];        // nms_mask * scores

// ---------------------------------------------------------------------------
// Kernel A: bbox_transform  (one thread per (r,k))
// ---------------------------------------------------------------------------
__global__ void bbox_kernel(const float* __restrict__ rois,
                            const float* __restrict__ deltas) {
    int t = blockIdx.x * blockDim.x + threadIdx.x;
    if (t >= R * K) return;
    int r = t / K;
    int k = t - r * K;

    float x1 = rois[r * 4 + 0];
    float y1 = rois[r * 4 + 1];
    float x2 = rois[r * 4 + 2];
    float y2 = rois[r * 4 + 3];

    float w  = x2 - x1 + 1.0f;
    float h  = y2 - y1 + 1.0f;
    float cx = x1 + 0.5f * w;
    float cy = y1 + 0.5f * h;

    const float* d = deltas + r * (4 * K) + 4 * k;
    float dx = d[0] / 10.0f;
    float dy = d[1] / 10.0f;
    float dw = fminf(d[2] / 5.0f, XFORM_CLIP);
    float dh = fminf(d[3] / 5.0f, XFORM_CLIP);

    float pcx = dx * w + cx;
    float pcy = dy * h + cy;
    float pw  = expf(dw) * w;
    float ph  = expf(dh) * h;

    float ox1 = fminf(fmaxf(pcx - 0.5f * pw, 0.0f), IM_W_M1);
    float oy1 = fminf(fmaxf(pcy - 0.5f * ph, 0.0f), IM_H_M1);
    float ox2 = fminf(fmaxf(pcx + 0.5f * pw - 1.0f, 0.0f), IM_W_M1);
    float oy2 = fminf(fmaxf(pcy + 0.5f * ph - 1.0f, 0.0f), IM_H_M1);

    reinterpret_cast<float4*>(g_boxes)[t] = make_float4(ox1, oy1, ox2, oy2);
}

// ---------------------------------------------------------------------------
// Kernel B: per-class NMS.  One block per class, 256 threads.
// Stable descending sort via uint64 key = (~score_bits << 32) | idx,
// sorted ascending (scores are positive softmax values so float bits are
// order-preserving).  This exactly reproduces jnp.argsort(-scores) stability.
// ---------------------------------------------------------------------------
__global__ void nms_kernel(const float* __restrict__ scores) {
    const int c = blockIdx.x;
    const int tid = threadIdx.x;

    __shared__ unsigned long long skey[R];   // 4 KB
    __shared__ float4 sbox[R];               // 8 KB  (indexed by ORIGINAL idx)
    __shared__ float  sarea[R];              // 2 KB
    __shared__ unsigned smask[R * 16];       // 32 KB suppression bitmask
    __shared__ unsigned skeepw[16];

    // Load
    for (int r = tid; r < R; r += blockDim.x) {
        float sc = scores[r * K + c];
        unsigned sb = __float_as_uint(sc);
        skey[r] = ((unsigned long long)(~sb) << 32) | (unsigned)r;
        float4 b = reinterpret_cast<const float4*>(g_boxes)[r * K + c];
        sbox[r] = b;
        sarea[r] = (b.z - b.x + 1.0f) * (b.w - b.y + 1.0f);
    }
    __syncthreads();

    // Bitonic sort (ascending uint64 => score desc, idx asc)
    for (int kk = 2; kk <= R; kk <<= 1) {
        for (int j = kk >> 1; j > 0; j >>= 1) {
            for (int i = tid; i < R; i += blockDim.x) {
                int ixj = i ^ j;
                if (ixj > i) {
                    bool up = ((i & kk) == 0);
                    unsigned long long a = skey[i], b = skey[ixj];
                    if ((a > b) == up) { skey[i] = b; skey[ixj] = a; }
                }
            }
            __syncthreads();
        }
    }

    // Suppression bitmask: smask[i*16+w] bit b  <=>  iou(sorted_i, sorted_{32w+b}) > thr
    for (int widx = tid; widx < R * 16; widx += blockDim.x) {
        int i = widx >> 4;
        int w = widx & 15;
        int oi = (unsigned)skey[i];
        float4 bi = sbox[oi];
        float ai = sarea[oi];
        unsigned bits = 0;
#pragma unroll 8
        for (int b = 0; b < 32; ++b) {
            int j = (w << 5) | b;
            int oj = (unsigned)skey[j];
            float4 bj = sbox[oj];
            float xx1 = fmaxf(bi.x, bj.x);
            float yy1 = fmaxf(bi.y, bj.y);
            float xx2 = fminf(bi.z, bj.z);
            float yy2 = fminf(bi.w, bj.w);
            float iw = fmaxf(xx2 - xx1 + 1.0f, 0.0f);
            float ih = fmaxf(yy2 - yy1 + 1.0f, 0.0f);
            float inter = iw * ih;
            float iou = inter / (ai + sarea[oj] - inter);
            if (iou > NMS_THRESH) bits |= (1u << b);
        }
        smask[widx] = bits;
    }
    __syncthreads();

    // Greedy scan on one warp: lane w (w<16) owns removal word w.
    if (tid < 32) {
        unsigned remv = 0, kw = 0;
        int lane = tid;
        for (int i = 0; i < R; ++i) {
            unsigned rw = __shfl_sync(0xffffffffu, remv, i >> 5);
            bool removed = (rw >> (i & 31)) & 1u;
            if (!removed) {
                if (lane == (i >> 5)) kw |= (1u << (i & 31));
                if (lane < 16) remv |= smask[i * 16 + lane];
            }
        }
        // POST_NMS_TOPN clamp: keep first 300 kept (in sorted order)
        int cnt = (lane < 16) ? __popc(kw) : 0;
        int incl = cnt;
        for (int off = 1; off < 16; off <<= 1) {
            int v = __shfl_up_sync(0xffffffffu, incl, off);
            if (lane >= off) incl += v;
        }
        int excl = incl - cnt;
        if (lane < 16) {
            if (excl >= POST_NMS_TOPN) {
                kw = 0;
            } else if (excl + cnt > POST_NMS_TOPN) {
                int allowed = POST_NMS_TOPN - excl;
                while (cnt > allowed) {
                    int hb = 31 - __clz(kw);
                    kw &= ~(1u << hb);
                    --cnt;
                }
            }
            skeepw[lane] = kw;
        }
    }
    __syncthreads();

    // Class validity: c != 0 and max raw score > thresh (sorted pos 0)
    float maxsc = __uint_as_float(~(unsigned)(skey[0] >> 32));
    bool cvalid = (c != 0) && (maxsc > SCORE_THRESH);

    // Scatter masked scores back to original row order
    for (int p = tid; p < R; p += blockDim.x) {
        unsigned long long kk = skey[p];
        int orig = (unsigned)kk;
        float sc = __uint_as_float(~(unsigned)(kk >> 32));
        bool kept = (skeepw[p >> 5] >> (p & 31)) & 1u;
        g_dist[orig * K + c] = (cvalid && kept) ? sc : 0.0f;
    }
}

// ---------------------------------------------------------------------------
// Kernel C: per-row max/argmax, stable top-100 sort, output write.
// Single block, 512 threads.
// ---------------------------------------------------------------------------
__global__ void finalize_kernel(float* __restrict__ out, int out_size) {
    __shared__ unsigned long long skey[R];
    __shared__ int slabel[R];
    const int r = threadIdx.x;

    // dists_all[r][0] is always 0 (class 0 invalid); strict > reproduces
    // first-occurrence argmax; all-zero row -> label 0, score 0.
    float best = 0.0f;
    int label = 0;
    const float* row = g_dist + r * K;
    for (int c = 1; c < K; ++c) {
        float v = row[c];
        if (v > best) { best = v; label = c; }
    }
    skey[r] = ((unsigned long long)(~__float_as_uint(best)) << 32) | (unsigned)r;
    slabel[r] = label;
    __syncthreads();

    // Bitonic sort ascending (score desc, row asc)  — matches stable argsort
    for (int kk = 2; kk <= R; kk <<= 1) {
        for (int j = kk >> 1; j > 0; j >>= 1) {
            int ixj = r ^ j;
            if (ixj > r) {
                bool up = ((r & kk) == 0);
                unsigned long long a = skey[r], b = skey[ixj];
                if ((a > b) == up) { skey[r] = b; skey[ixj] = a; }
            }
            __syncthreads();
        }
    }

    if (r < MAX_PER_IMG) {
        unsigned long long kk = skey[r];
        int top = (unsigned)kk;
        float sc = __uint_as_float(~(unsigned)(kk >> 32));
        int lab = slabel[top];
        bool valid = sc > SCORE_THRESH;
        float4 b = reinterpret_cast<const float4*>(g_boxes)[top * K + lab];

        float osc = valid ? sc : 0.0f;
        float bx1 = valid ? b.x : 0.0f;
        float by1 = valid ? b.y : 0.0f;
        float bx2 = valid ? b.z : 0.0f;
        float by2 = valid ? b.w : 0.0f;

        int base = r * 5;
        if (base + 4 < out_size) {
            out[base + 0] = osc;
            out[base + 1] = bx1;
            out[base + 2] = by1;
            out[base + 3] = bx2;
            out[base + 4] = by2;
        }
        if (MAX_PER_IMG * 5 + r < out_size) out[MAX_PER_IMG * 5 + r] = (float)lab;
        if (MAX_PER_IMG * 6 + r < out_size) out[MAX_PER_IMG * 6 + r] = (float)top;
    }
}

// ---------------------------------------------------------------------------
extern "C" void kernel_launch(void* const* d_in, const int* in_sizes, int n_in,
                              void* d_out, int out_size) {
    const float* rois   = (const float*)d_in[0];
    const float* deltas = (const float*)d_in[1];
    const float* scores = (const float*)d_in[2];
    float* out = (float*)d_out;
    (void)in_sizes; (void)n_in;

    bbox_kernel<<<(R * K + 255) / 256, 256>>>(rois, deltas);
    nms_kernel<<<K, 256>>>(scores);
    finalize_kernel<<<1, R>>>(out, out_size);
}

// round 4
// speedup vs baseline: 2.2567x; 2.2567x over previous
#include <cuda_runtime.h>
#include <cuda_bf16.h>
#include <math.h>

#define R 512
#define K 81
#define NMS_THRESH 0.5f
#define SCORE_THRESH 0.001f
#define MAX_PER_IMG 100
#define POST_NMS_TOPN 300
#define XFORM_CLIP 4.135166556742356f  /* log(1000/16) */
#define IM_W_M1 1332.0f
#define IM_H_M1 799.0f

// Scratch (no allocation allowed). Transposed: [c][r] for coalesced finalize reads.
__device__ float g_dist[K * R];

// Shared box transform — MUST be the single definition used by both kernels so
// rounding is identical everywhere (matches the R1 kernel that passed).
__device__ __forceinline__ float4 xform_box(const float* __restrict__ rois,
                                            const float* __restrict__ deltas,
                                            int r, int k) {
    float4 roi = reinterpret_cast<const float4*>(rois)[r];
    float4 dl  = *reinterpret_cast<const float4*>(deltas + r * (4 * K) + 4 * k);

    float w  = roi.z - roi.x + 1.0f;
    float h  = roi.w - roi.y + 1.0f;
    float cx = roi.x + 0.5f * w;
    float cy = roi.y + 0.5f * h;

    float dx = dl.x / 10.0f;
    float dy = dl.y / 10.0f;
    float dw = fminf(dl.z / 5.0f, XFORM_CLIP);
    float dh = fminf(dl.w / 5.0f, XFORM_CLIP);

    float pcx = dx * w + cx;
    float pcy = dy * h + cy;
    float pw  = expf(dw) * w;
    float ph  = expf(dh) * h;

    float ox1 = fminf(fmaxf(pcx - 0.5f * pw, 0.0f), IM_W_M1);
    float oy1 = fminf(fmaxf(pcy - 0.5f * ph, 0.0f), IM_H_M1);
    float ox2 = fminf(fmaxf(pcx + 0.5f * pw - 1.0f, 0.0f), IM_W_M1);
    float oy2 = fminf(fmaxf(pcy + 0.5f * ph - 1.0f, 0.0f), IM_H_M1);
    return make_float4(ox1, oy1, ox2, oy2);
}

// ---------------------------------------------------------------------------
// Fused per-class kernel: bbox transform + stable sort + NMS.
// One block per class, 512 threads (1 row per thread).
// ---------------------------------------------------------------------------
__global__ __launch_bounds__(R, 1) void nms_kernel(const float* __restrict__ rois,
                                                   const float* __restrict__ deltas,
                                                   const float* __restrict__ scores) {
    const int c   = blockIdx.x;
    const int tid = threadIdx.x;           // == row index, 0..511

    __shared__ unsigned long long skey[R];   // 4 KB  (~score_bits<<32 | idx)
    __shared__ float4 sboxS[R];              // 8 KB  sorted-order boxes
    __shared__ float  sareaS[R];             // 2 KB  sorted-order areas
    __shared__ unsigned skeepw[16];
    __shared__ unsigned smask[R * 16];       // 32 KB; head aliased pre-sort:
    float4* sboxO = reinterpret_cast<float4*>(smask);            // 8 KB
    float*  sareaO = reinterpret_cast<float*>(smask + 2048 * 2); // +2 KB (offset 8KB)

    // Phase 1: compute this row's box + key
    {
        float4 b = xform_box(rois, deltas, tid, c);
        sboxO[tid]  = b;
        sareaO[tid] = (b.z - b.x + 1.0f) * (b.w - b.y + 1.0f);
        unsigned sb = __float_as_uint(scores[tid * K + c]);
        skey[tid] = ((unsigned long long)(~sb) << 32) | (unsigned)tid;
    }
    __syncthreads();

    // Phase 2: bitonic sort ascending (=> score desc, idx asc; stable argsort)
    for (int kk = 2; kk <= R; kk <<= 1) {
        for (int j = kk >> 1; j > 0; j >>= 1) {
            int ixj = tid ^ j;
            if (ixj > tid) {
                bool up = ((tid & kk) == 0);
                unsigned long long a = skey[tid], b = skey[ixj];
                if ((a > b) == up) { skey[tid] = b; skey[ixj] = a; }
            }
            __syncthreads();
        }
    }

    // Phase 3: gather boxes into sorted order (registers), then publish
    int   oi = (unsigned)skey[tid];
    float4 bi = sboxO[oi];
    float  ai = sareaO[oi];
    __syncthreads();                 // all gathers done before alias reuse
    sboxS[tid]  = bi;
    sareaS[tid] = ai;
    __syncthreads();

    // Phase 4: suppression bitmask, upper-triangle words only.
    // Row i = tid needs words w >= i>>5 (earlier bits never consulted).
    // All lanes read the same sboxS[j] -> LDS broadcast, conflict-free.
    {
        const int wstart = tid >> 5;          // uniform per warp
        for (int w = wstart; w < 16; ++w) {
            unsigned bits = 0;
#pragma unroll
            for (int b = 0; b < 32; ++b) {
                int j = (w << 5) | b;
                float4 bj = sboxS[j];
                float  aj = sareaS[j];
                float xx1 = fmaxf(bi.x, bj.x);
                float yy1 = fmaxf(bi.y, bj.y);
                float xx2 = fminf(bi.z, bj.z);
                float yy2 = fminf(bi.w, bj.w);
                float iw = fmaxf(xx2 - xx1 + 1.0f, 0.0f);
                float ih = fmaxf(yy2 - yy1 + 1.0f, 0.0f);
                float inter = iw * ih;
                float iou = inter / (ai + aj - inter);
                if (iou > NMS_THRESH) bits |= (1u << b);
            }
            smask[tid * 16 + w] = bits;
        }
    }
    __syncthreads();

    // Phase 5: greedy scan on one warp; lane w<16 owns removal word w.
    if (tid < 32) {
        unsigned remv = 0, kw = 0;
        const int lane = tid;
        for (int i = 0; i < R; ++i) {
            // prefetchable, independent of the shfl below
            unsigned rowv = 0;
            if (lane < 16 && lane >= (i >> 5)) rowv = smask[i * 16 + lane];
            unsigned rw = __shfl_sync(0xffffffffu, remv, i >> 5);
            if (!((rw >> (i & 31)) & 1u)) {
                if (lane == (i >> 5)) kw |= (1u << (i & 31));
                remv |= rowv;
            }
        }
        // POST_NMS_TOPN clamp: keep first 300 kept (sorted order)
        int cnt = (lane < 16) ? __popc(kw) : 0;
        int incl = cnt;
        for (int off = 1; off < 16; off <<= 1) {
            int v = __shfl_up_sync(0xffffffffu, incl, off);
            if (lane >= off) incl += v;
        }
        int excl = incl - cnt;
        if (lane < 16) {
            if (excl >= POST_NMS_TOPN) {
                kw = 0;
            } else if (excl + cnt > POST_NMS_TOPN) {
                int allowed = POST_NMS_TOPN - excl;
                while (cnt > allowed) {
                    int hb = 31 - __clz(kw);
                    kw &= ~(1u << hb);
                    --cnt;
                }
            }
            skeepw[lane] = kw;
        }
    }
    __syncthreads();

    // Phase 6: class validity (raw max = sorted pos 0) + scatter masked scores
    float maxsc = __uint_as_float(~(unsigned)(skey[0] >> 32));
    bool cvalid = (c != 0) && (maxsc > SCORE_THRESH);

    {
        unsigned long long kk = skey[tid];
        int orig = (unsigned)kk;
        float sc = __uint_as_float(~(unsigned)(kk >> 32));
        bool kept = (skeepw[tid >> 5] >> (tid & 31)) & 1u;
        g_dist[c * R + orig] = (cvalid && kept) ? sc : 0.0f;
    }
}

// ---------------------------------------------------------------------------
// Finalize: per-row max/argmax (coalesced over transposed g_dist), stable
// top-100 sort, recompute the 100 output boxes, write results.
// ---------------------------------------------------------------------------
__global__ __launch_bounds__(R, 1) void finalize_kernel(const float* __restrict__ rois,
                                                        const float* __restrict__ deltas,
                                                        float* __restrict__ out,
                                                        int out_size) {
    __shared__ unsigned long long skey[R];
    __shared__ int slabel[R];
    const int r = threadIdx.x;

    // strict > reproduces first-occurrence argmax; class 0 always invalid.
    float best = 0.0f;
    int label = 0;
    for (int c = 1; c < K; ++c) {
        float v = g_dist[c * R + r];       // coalesced across lanes
        if (v > best) { best = v; label = c; }
    }
    skey[r] = ((unsigned long long)(~__float_as_uint(best)) << 32) | (unsigned)r;
    slabel[r] = label;
    __syncthreads();

    for (int kk = 2; kk <= R; kk <<= 1) {
        for (int j = kk >> 1; j > 0; j >>= 1) {
            int ixj = r ^ j;
            if (ixj > r) {
                bool up = ((r & kk) == 0);
                unsigned long long a = skey[r], b = skey[ixj];
                if ((a > b) == up) { skey[r] = b; skey[ixj] = a; }
            }
            __syncthreads();
        }
    }

    if (r < MAX_PER_IMG) {
        unsigned long long kk = skey[r];
        int top = (unsigned)kk;
        float sc = __uint_as_float(~(unsigned)(kk >> 32));
        int lab = slabel[top];
        bool valid = sc > SCORE_THRESH;
        float4 b = xform_box(rois, deltas, top, lab);

        float osc = valid ? sc : 0.0f;
        float bx1 = valid ? b.x : 0.0f;
        float by1 = valid ? b.y : 0.0f;
        float bx2 = valid ? b.z : 0.0f;
        float by2 = valid ? b.w : 0.0f;

        int base = r * 5;
        if (base + 4 < out_size) {
            out[base + 0] = osc;
            out[base + 1] = bx1;
            out[base + 2] = by1;
            out[base + 3] = bx2;
            out[base + 4] = by2;
        }
        if (MAX_PER_IMG * 5 + r < out_size) out[MAX_PER_IMG * 5 + r] = (float)lab;
        if (MAX_PER_IMG * 6 + r < out_size) out[MAX_PER_IMG * 6 + r] = (float)top;
    }
}

// ---------------------------------------------------------------------------
extern "C" void kernel_launch(void* const* d_in, const int* in_sizes, int n_in,
                              void* d_out, int out_size) {
    const float* rois   = (const float*)d_in[0];
    const float* deltas = (const float*)d_in[1];
    const float* scores = (const float*)d_in[2];
    float* out = (float*)d_out;
    (void)in_sizes; (void)n_in;

    nms_kernel<<<K, R>>>(rois, deltas, scores);
    finalize_kernel<<<1, R>>>(rois, deltas, out, out_size);
}

// round 5
// speedup vs baseline: 8.3106x; 3.6826x over previous
#include <cuda_runtime.h>
#include <cuda_bf16.h>
#include <math.h>

#define R 512
#define K 81
#define SCORE_THRESH 0.001f
#define MAX_PER_IMG 100
#define POST_NMS_TOPN 300
#define XFORM_CLIP 4.135166556742356f  /* log(1000/16) */
#define IM_W_M1 1332.0f
#define IM_H_M1 799.0f
#define TRI_TOTAL 4352                 /* sum_{w=0}^{15} 32*(w+1) */

// Scratch (no allocation allowed). Transposed: [c][r] for coalesced finalize reads.
__device__ float g_dist[K * R];

// ---------------------------------------------------------------------------
// Box transform — single definition, identical rounding everywhere.
// ---------------------------------------------------------------------------
__device__ __forceinline__ float4 xform_box(const float* __restrict__ rois,
                                            const float* __restrict__ deltas,
                                            int r, int k) {
    float4 roi = reinterpret_cast<const float4*>(rois)[r];
    float4 dl  = *reinterpret_cast<const float4*>(deltas + r * (4 * K) + 4 * k);

    float w  = roi.z - roi.x + 1.0f;
    float h  = roi.w - roi.y + 1.0f;
    float cx = roi.x + 0.5f * w;
    float cy = roi.y + 0.5f * h;

    float dx = dl.x / 10.0f;
    float dy = dl.y / 10.0f;
    float dw = fminf(dl.z / 5.0f, XFORM_CLIP);
    float dh = fminf(dl.w / 5.0f, XFORM_CLIP);

    float pcx = dx * w + cx;
    float pcy = dy * h + cy;
    float pw  = expf(dw) * w;
    float ph  = expf(dh) * h;

    float ox1 = fminf(fmaxf(pcx - 0.5f * pw, 0.0f), IM_W_M1);
    float oy1 = fminf(fmaxf(pcy - 0.5f * ph, 0.0f), IM_H_M1);
    float ox2 = fminf(fmaxf(pcx + 0.5f * pw - 1.0f, 0.0f), IM_W_M1);
    float oy2 = fminf(fmaxf(pcy + 0.5f * ph - 1.0f, 0.0f), IM_H_M1);
    return make_float4(ox1, oy1, ox2, oy2);
}

// ---------------------------------------------------------------------------
// Hybrid bitonic sort of 512 unique uint64 keys, ascending.
// Intra-warp stages (j<=16) via 64-bit shfl (no barriers); cross-warp via shared.
// ---------------------------------------------------------------------------
__device__ __forceinline__ unsigned long long cswap_shfl(unsigned long long key,
                                                         int tid, int kk, int j) {
    unsigned long long pk = __shfl_xor_sync(0xffffffffu, key, j);
    bool asc   = ((tid & kk) == 0);
    bool lower = ((tid & j) == 0);
    bool cmp   = key > pk;
    bool take  = ((cmp == asc) == lower);
    return take ? pk : key;
}

__device__ __forceinline__ void sort512(unsigned long long* skey, int tid) {
    unsigned long long key = skey[tid];
    // kk = 2..32 entirely intra-warp
#pragma unroll
    for (int kk = 2; kk <= 32; kk <<= 1)
#pragma unroll
        for (int j = kk >> 1; j > 0; j >>= 1)
            key = cswap_shfl(key, tid, kk, j);
    skey[tid] = key;
    __syncthreads();
    // kk = 64..512: cross-warp passes in shared, j<=16 tail via shfl
#pragma unroll
    for (int kk = 64; kk <= 512; kk <<= 1) {
        for (int j = kk >> 1; j >= 32; j >>= 1) {
            int ixj = tid ^ j;
            if (ixj > tid) {
                bool up = ((tid & kk) == 0);
                unsigned long long a = skey[tid], b = skey[ixj];
                if ((a > b) == up) { skey[tid] = b; skey[ixj] = a; }
            }
            __syncthreads();
        }
        key = skey[tid];
#pragma unroll
        for (int j = 16; j > 0; j >>= 1)
            key = cswap_shfl(key, tid, kk, j);
        skey[tid] = key;
        __syncthreads();
    }
}

// ---------------------------------------------------------------------------
// Fused per-class kernel: bbox transform + stable sort + NMS.
// One block per class, 512 threads.
// ---------------------------------------------------------------------------
__global__ __launch_bounds__(R, 1) void nms_kernel(const float* __restrict__ rois,
                                                   const float* __restrict__ deltas,
                                                   const float* __restrict__ scores) {
    const int c   = blockIdx.x;
    const int tid = threadIdx.x;

    __shared__ unsigned long long skey[R];   // 4 KB  (~score_bits<<32 | idx)
    __shared__ float4 sboxS[R];              // 8 KB  sorted-order boxes
    __shared__ float  sareaS[R];             // 2 KB  sorted-order areas
    __shared__ unsigned skeepw[16];
    __shared__ unsigned smask[R * 16];       // 32 KB; head aliased pre-sort:
    float4* sboxO = reinterpret_cast<float4*>(smask);            // 8 KB
    float*  sareaO = reinterpret_cast<float*>(smask + 2048 * 2); // +2 KB

    // Phase 1: box + stable sort key for this row
    {
        float4 b = xform_box(rois, deltas, tid, c);
        sboxO[tid]  = b;
        sareaO[tid] = (b.z - b.x + 1.0f) * (b.w - b.y + 1.0f);
        unsigned sb = __float_as_uint(scores[tid * K + c]);
        skey[tid] = ((unsigned long long)(~sb) << 32) | (unsigned)tid;
    }
    __syncthreads();

    // Phase 2: sort (ascending uint64 => score desc, idx asc)
    sort512(skey, tid);

    // Phase 3: gather boxes into sorted order, republish
    {
        int oi = (unsigned)skey[tid];
        float4 bi = sboxO[oi];
        float  ai = sareaO[oi];
        __syncthreads();                 // gathers done before alias reuse
        sboxS[tid]  = bi;
        sareaS[tid] = ai;
    }
    __syncthreads();

    // Phase 4: suppression bitmask, balanced triangle (columns w >= i>>5).
    // Flat index f over column-major triangle; column w holds rows [0, 32(w+1)).
    for (int f = tid; f < TRI_TOTAL; f += R) {
        int w = (int)((sqrtf(1.0f + (float)f * 0.25f) - 1.0f) * 0.5f);
        while (16 * (w + 1) * (w + 2) <= f) ++w;
        while (16 * w * (w + 1) > f) --w;
        int i = f - 16 * w * (w + 1);

        float4 bi = sboxS[i];
        float  ai = sareaS[i];
        unsigned bits = 0;
#pragma unroll
        for (int b = 0; b < 32; ++b) {
            int j = (w << 5) | b;
            float4 bj = sboxS[j];            // broadcast across warp
            float  aj = sareaS[j];
            float xx1 = fmaxf(bi.x, bj.x);
            float yy1 = fmaxf(bi.y, bj.y);
            float xx2 = fminf(bi.z, bj.z);
            float yy2 = fminf(bi.w, bj.w);
            float iw = fmaxf(xx2 - xx1 + 1.0f, 0.0f);
            float ih = fmaxf(yy2 - yy1 + 1.0f, 0.0f);
            float inter = iw * ih;
            float uni = ai + aj - inter;     // > 0 always (areas >= 1)
            // iou > 0.5  <=>  2*inter > union   (division-free)
            if (inter + inter > uni) bits |= (1u << b);
        }
        smask[i * 16 + w] = bits;
    }
    __syncthreads();

    // Phase 5: greedy scan, chunked. Lane w (<16) owns removal word w.
    if (tid < 32) {
        const int lane = tid;
        unsigned remv = 0, kw = 0;
        for (int ch = 0; ch < 16; ++ch) {
            unsigned kwc = 0;
            if (lane == ch) {
                unsigned diag[32];
#pragma unroll
                for (int j = 0; j < 32; ++j)
                    diag[j] = smask[(ch * 32 + j) * 16 + ch];
#pragma unroll
                for (int j = 0; j < 32; ++j) {
                    // s = all-ones if row j already suppressed
                    unsigned s = (unsigned)(((int)(remv << (31 - j))) >> 31);
                    kwc  |= (~s) & (1u << j);
                    remv |= diag[j] & ~s;
                }
                kw = kwc;
            }
            kwc = __shfl_sync(0xffffffffu, kwc, ch);
            if (lane > ch && lane < 16) {
#pragma unroll
                for (int j = 0; j < 32; ++j) {
                    unsigned live = (kwc >> j) & 1u;
                    remv |= smask[(ch * 32 + j) * 16 + lane] & (0u - live);
                }
            }
        }
        // POST_NMS_TOPN clamp: keep first 300 kept (sorted order)
        int cnt = (lane < 16) ? __popc(kw) : 0;
        int incl = cnt;
        for (int off = 1; off < 16; off <<= 1) {
            int v = __shfl_up_sync(0xffffffffu, incl, off);
            if (lane >= off) incl += v;
        }
        int excl = incl - cnt;
        if (lane < 16) {
            if (excl >= POST_NMS_TOPN) {
                kw = 0;
            } else if (excl + cnt > POST_NMS_TOPN) {
                int allowed = POST_NMS_TOPN - excl;
                while (cnt > allowed) {
                    int hb = 31 - __clz(kw);
                    kw &= ~(1u << hb);
                    --cnt;
                }
            }
            skeepw[lane] = kw;
        }
    }
    __syncthreads();

    // Phase 6: class validity + scatter masked scores (transposed layout)
    {
        float maxsc = __uint_as_float(~(unsigned)(skey[0] >> 32));
        bool cvalid = (c != 0) && (maxsc > SCORE_THRESH);
        unsigned long long kk = skey[tid];
        int orig = (unsigned)kk;
        float sc = __uint_as_float(~(unsigned)(kk >> 32));
        bool kept = (skeepw[tid >> 5] >> (tid & 31)) & 1u;
        g_dist[c * R + orig] = (cvalid && kept) ? sc : 0.0f;
    }
}

// ---------------------------------------------------------------------------
// Finalize: per-row max/argmax, stable top-100 sort, write outputs.
// ---------------------------------------------------------------------------
__global__ __launch_bounds__(R, 1) void finalize_kernel(const float* __restrict__ rois,
                                                        const float* __restrict__ deltas,
                                                        float* __restrict__ out,
                                                        int out_size) {
    __shared__ unsigned long long skey[R];
    __shared__ int slabel[R];
    const int r = threadIdx.x;

    // Two independent chains; strict > keeps first occurrence; class 0 invalid.
    float b1 = 0.0f, b2 = 0.0f;
    int l1 = 0, l2 = 0;
    for (int c = 1; c <= 40; ++c) {
        float v = g_dist[c * R + r];
        if (v > b1) { b1 = v; l1 = c; }
    }
    for (int c = 41; c < K; ++c) {
        float v = g_dist[c * R + r];
        if (v > b2) { b2 = v; l2 = c; }
    }
    float best = b1; int label = l1;
    if (b2 > b1) { best = b2; label = l2; }   // tie -> lower class (first occurrence)

    skey[r] = ((unsigned long long)(~__float_as_uint(best)) << 32) | (unsigned)r;
    slabel[r] = label;
    __syncthreads();

    sort512(skey, r);

    if (r < MAX_PER_IMG) {
        unsigned long long kk = skey[r];
        int top = (unsigned)kk;
        float sc = __uint_as_float(~(unsigned)(kk >> 32));
        int lab = slabel[top];
        bool valid = sc > SCORE_THRESH;
        float4 b = xform_box(rois, deltas, top, lab);

        float osc = valid ? sc : 0.0f;
        float bx1 = valid ? b.x : 0.0f;
        float by1 = valid ? b.y : 0.0f;
        float bx2 = valid ? b.z : 0.0f;
        float by2 = valid ? b.w : 0.0f;

        int base = r * 5;
        if (base + 4 < out_size) {
            out[base + 0] = osc;
            out[base + 1] = bx1;
            out[base + 2] = by1;
            out[base + 3] = bx2;
            out[base + 4] = by2;
        }
        if (MAX_PER_IMG * 5 + r < out_size) out[MAX_PER_IMG * 5 + r] = (float)lab;
        if (MAX_PER_IMG * 6 + r < out_size) out[MAX_PER_IMG * 6 + r] = (float)top;
    }
}

// ---------------------------------------------------------------------------
extern "C" void kernel_launch(void* const* d_in, const int* in_sizes, int n_in,
                              void* d_out, int out_size) {
    const float* rois   = (const float*)d_in[0];
    const float* deltas = (const float*)d_in[1];
    const float* scores = (const float*)d_in[2];
    float* out = (float*)d_out;
    (void)in_sizes; (void)n_in;

    nms_kernel<<<K, R>>>(rois, deltas, scores);
    finalize_kernel<<<1, R>>>(rois, deltas, out, out_size);
}